// round 9
// baseline (speedup 1.0000x reference)
#include <cuda_runtime.h>
#include <cuda_bf16.h>
#include <math.h>

// Problem constants
#define VV   32000
#define EE   500
#define HH   500
#define DD1  800
#define DD2  100
#define CC   2
#define BB   64
#define TT   400
#define G4H  2000            // 4*H
#define MM   (BB*TT)         // 25600 rows of the big GEMMs
#define NREC_BLOCKS 125      // 125 * 4 units = 500
#define GSZ  16384           // floats per group slice (128 quads x 32 b x 4) = 64KB
#define SLOT (2*GSZ)         // one h time-slot: both groups = 32768 floats (128KB)

// ---------------- scratch (device globals; no allocation allowed) ----------------
__device__ float g_xz [(size_t)MM * G4H];       // 204.8 MB, reused for layer1 and layer2
__device__ float g_hs1[(size_t)MM * HH];        // 51.2 MB (layer-1 h for SGEMM2)
__device__ float g_hrd[(size_t)(TT+1) * SLOT];  // 52.6 MB h history ring (read-optimized)
__device__ float g_d1 [BB * DD1];
__device__ float g_d2 [BB * DD2];
// flat barrier state: counter and sense on separate 128B lines, per group
__device__ unsigned g_gcnt[2][32];
__device__ unsigned g_gsns[2][32];
__device__ unsigned g_icnt[32];
__device__ unsigned g_isns[32];

// ---------------- packed f32x2 helpers ----------------
__device__ __forceinline__ unsigned long long dup2(float v){
    unsigned long long r;
    asm("mov.b64 %0, {%1, %1};" : "=l"(r) : "f"(v));
    return r;
}
__device__ __forceinline__ void fma2(unsigned long long &d,
                                     unsigned long long a,
                                     unsigned long long b){
    asm("fma.rn.f32x2 %0, %1, %2, %3;" : "=l"(d) : "l"(a), "l"(b), "l"(d));
}
__device__ __forceinline__ void unpk2(unsigned long long v, float &lo, float &hi){
    asm("mov.b64 {%0, %1}, %2;" : "=f"(lo), "=f"(hi) : "l"(v));
}

// =====================================================================
// SGEMM: C[M=25600, N=2000] = A[M,500] @ Bw[500,2000] + bias
// GATHER=1: A row m -> embed[X[b*T+t]] with m = t*64+b
// =====================================================================
template<int GATHER>
__global__ __launch_bounds__(256)
void sgemm_xz(const int* __restrict__ X, const float* __restrict__ A,
              const float* __restrict__ Bw, const float* __restrict__ bias,
              float* __restrict__ Cmat)
{
    __shared__ float As[8][128];
    __shared__ float Bs[8][128];

    const int tid = threadIdx.x;
    const int tx  = tid & 15;
    const int ty  = tid >> 4;
    const int m0  = blockIdx.y * 128;
    const int n0  = blockIdx.x * 128;

    const int ar  = tid >> 1;
    const int akq = (tid & 1) * 4;
    const float* arow_ptr;
    {
        int m = m0 + ar;
        if (GATHER){
            int t = m >> 6, b = m & 63;
            int tok = X[b * TT + t];
            arow_ptr = A + (size_t)tok * EE;
        } else {
            arow_ptr = A + (size_t)m * HH;
        }
    }
    const int bk = tid >> 5;
    const int bn = (tid & 31) * 4;

    unsigned long long acc[8][4];
    #pragma unroll
    for (int i = 0; i < 8; i++)
        #pragma unroll
        for (int j = 0; j < 4; j++) acc[i][j] = 0ULL;

    const float4 f40 = make_float4(0.f, 0.f, 0.f, 0.f);
    float4 aReg, bReg;
    {
        int k  = akq;
        aReg = (k < 500) ? *(const float4*)(arow_ptr + k) : f40;
        int kb = bk, n = n0 + bn;
        bReg = (kb < 500 && n < G4H) ? *(const float4*)(Bw + (size_t)kb * G4H + n) : f40;
    }

    const int KT = 63;
    for (int kt = 0; kt < KT; kt++){
        __syncthreads();
        As[akq+0][ar] = aReg.x; As[akq+1][ar] = aReg.y;
        As[akq+2][ar] = aReg.z; As[akq+3][ar] = aReg.w;
        *(float4*)(&Bs[bk][bn]) = bReg;
        __syncthreads();

        if (kt + 1 < KT){
            int k = (kt+1)*8 + akq;
            aReg = (k < 500) ? *(const float4*)(arow_ptr + k) : f40;
            int kb = (kt+1)*8 + bk, n = n0 + bn;
            bReg = (kb < 500 && n < G4H) ? *(const float4*)(Bw + (size_t)kb * G4H + n) : f40;
        }

        #pragma unroll
        for (int kk = 0; kk < 8; kk++){
            float4 a0 = *(const float4*)(&As[kk][ty*8]);
            float4 a1 = *(const float4*)(&As[kk][ty*8 + 4]);
            const unsigned long long* bp2 = (const unsigned long long*)(&Bs[kk][tx*8]);
            unsigned long long b0 = bp2[0], b1 = bp2[1], b2 = bp2[2], b3 = bp2[3];
            float av[8] = {a0.x,a0.y,a0.z,a0.w,a1.x,a1.y,a1.z,a1.w};
            #pragma unroll
            for (int i = 0; i < 8; i++){
                unsigned long long ad = dup2(av[i]);
                fma2(acc[i][0], ad, b0);
                fma2(acc[i][1], ad, b1);
                fma2(acc[i][2], ad, b2);
                fma2(acc[i][3], ad, b3);
            }
        }
    }

    const int nc = n0 + tx * 8;
    if (nc < G4H){
        float4 bb0 = *(const float4*)(bias + nc);
        float4 bb1 = *(const float4*)(bias + nc + 4);
        #pragma unroll
        for (int i = 0; i < 8; i++){
            int m = m0 + ty*8 + i;
            float o[8];
            unpk2(acc[i][0], o[0], o[1]);
            unpk2(acc[i][1], o[2], o[3]);
            unpk2(acc[i][2], o[4], o[5]);
            unpk2(acc[i][3], o[6], o[7]);
            float4 r0 = make_float4(o[0]+bb0.x, o[1]+bb0.y, o[2]+bb0.z, o[3]+bb0.w);
            float4 r1 = make_float4(o[4]+bb1.x, o[5]+bb1.y, o[6]+bb1.z, o[7]+bb1.w);
            float* cp = Cmat + (size_t)m * G4H + nc;
            *(float4*)(cp)     = r0;
            *(float4*)(cp + 4) = r1;
        }
    }
}

// =====================================================================
// Per-group flat grid barrier (R6, proven). bar.sync orders the group's weak
// stores before lt0's gpu-scope acq_rel arrive; pollers acquire-load the sense.
// =====================================================================
__device__ __forceinline__ void group_barrier(int g, int lt, unsigned &sense)
{
    asm volatile("bar.sync %0, 128;" :: "r"(3 + g) : "memory");
    if (lt == 0){
        unsigned target = sense + 1u;
        unsigned old;
        asm volatile("atom.acq_rel.gpu.global.add.u32 %0, [%1], %2;"
                     : "=r"(old) : "l"(&g_gcnt[g][0]), "r"(1u) : "memory");
        if (old == (unsigned)(NREC_BLOCKS - 1)){
            asm volatile("st.relaxed.gpu.global.u32 [%0], %1;"
                         :: "l"(&g_gcnt[g][0]), "r"(0u) : "memory");
            asm volatile("st.release.gpu.global.u32 [%0], %1;"
                         :: "l"(&g_gsns[g][0]), "r"(target) : "memory");
        } else {
            unsigned v;
            do {
                asm volatile("ld.acquire.gpu.global.u32 %0, [%1];"
                             : "=r"(v) : "l"(&g_gsns[g][0]) : "memory");
            } while ((int)(v - target) < 0);
        }
        sense = target;
    }
    asm volatile("bar.sync %0, 128;" :: "r"(3 + g) : "memory");
}

// =====================================================================
// Persistent LSTM recurrence, L1-cache-mediated h exchange.
// 125 blocks x 256 threads (1 block/SM by wave-1 placement), 2 batch-groups.
// h(t) is written to time-slot t+1 of g_hrd (fresh addresses every step ->
// no stale-L1 hazard), quad-packed: hrd[slot][g][q*128 + bl*4 + (k&3)].
// Readers use plain LDG.128: first warp of a (group,unit-set) misses to L2
// (~125KB/SM/step), sibling warps hit L1 (~196KB available, smem is 32KB).
// No SMEM staging, no cp.async, 2 bar.syncs/step fewer than R6.
// =====================================================================
__global__ void lstm_rec(const float* __restrict__ xz, const float* __restrict__ Wh,
                         float* __restrict__ hs_out, int store_hs,
                         float* __restrict__ hrd)
{
    extern __shared__ float wsm[];     // 8000 floats (32 KB)

    const int tid = threadIdx.x;
    const int g   = tid >> 7;          // batch group 0/1
    const int lt  = tid & 127;         // lane within group
    const int bl  = lt & 31;           // batch within group
    const int u   = (lt >> 5) & 3;     // unit within block slice
    const int u0  = blockIdx.x * 4;
    const int uu  = u0 + u;
    const int b   = g * 32 + bl;       // global batch

    unsigned gsense = 0, isense = 0;
    if (lt == 0)
        asm volatile("ld.relaxed.gpu.global.u32 %0, [%1];" : "=r"(gsense) : "l"(&g_gsns[g][0]) : "memory");
    if (tid == 0)
        asm volatile("ld.relaxed.gpu.global.u32 %0, [%1];" : "=r"(isense) : "l"(&g_isns[0]) : "memory");

    // cache weight slice: wsm[k*16 + uw*4 + gate] = Wh[k*2000 + gate*500 + u0+uw]
    for (int idx = tid; idx < 500 * 16; idx += 256){
        int k = idx >> 4, r = idx & 15;
        int uw = r >> 2, gg = r & 3;
        wsm[idx] = Wh[(size_t)k * G4H + gg * HH + u0 + uw];
    }
    // zero time-slot 0 (h(-1) = 0), incl. pad quads
    {
        int gt = blockIdx.x * 256 + tid;
        for (int i = gt; i < SLOT; i += NREC_BLOCKS * 256)
            hrd[i] = 0.f;
    }
    // init: full-grid single-counter barrier (one-time)
    __syncthreads();
    if (tid == 0){
        unsigned target = isense + 1u, old;
        asm volatile("atom.acq_rel.gpu.global.add.u32 %0, [%1], %2;"
                     : "=r"(old) : "l"(&g_icnt[0]), "r"(1u) : "memory");
        if (old == (unsigned)(NREC_BLOCKS - 1)){
            asm volatile("st.relaxed.gpu.global.u32 [%0], %1;" :: "l"(&g_icnt[0]), "r"(0u) : "memory");
            asm volatile("st.release.gpu.global.u32 [%0], %1;" :: "l"(&g_isns[0]), "r"(target) : "memory");
        } else {
            unsigned v;
            do {
                asm volatile("ld.acquire.gpu.global.u32 %0, [%1];" : "=r"(v) : "l"(&g_isns[0]) : "memory");
            } while ((int)(v - target) < 0);
        }
    }
    __syncthreads();

    float cst = 0.f;
    const int hwr = g * GSZ + (uu >> 2) * 128 + bl * 4 + (uu & 3);   // write offset in slot
    const float* xzb = xz + (size_t)b * G4H + uu;

    for (int t = 0; t < TT; t++){
        const float* hq = hrd + (size_t)t * SLOT + g * GSZ + bl * 4;   // read slot t
        float*       hw = hrd + (size_t)(t + 1) * SLOT + hwr;          // write slot t+1

        // xz loads (DRAM) issued first; consumed after the 500-MAC chain
        size_t mrow = (size_t)t * BB * G4H;
        float xi = __ldcs(xzb + mrow);
        float xj = __ldcs(xzb + mrow + 500);
        float xf = __ldcs(xzb + mrow + 1000);
        float xo = __ldcs(xzb + mrow + 1500);

        unsigned long long aij = 0ULL, afo = 0ULL;
        #pragma unroll 4
        for (int q = 0; q < 125; q++){
            float4 h4 = *(const float4*)(hq + q * 128);     // LDG.128 (L1-cached)
            const float* wq = wsm + q * 64 + u * 4;
            ulonglong2 w0 = *(const ulonglong2*)(wq);
            ulonglong2 w1 = *(const ulonglong2*)(wq + 16);
            ulonglong2 w2 = *(const ulonglong2*)(wq + 32);
            ulonglong2 w3 = *(const ulonglong2*)(wq + 48);
            fma2(aij, dup2(h4.x), w0.x); fma2(afo, dup2(h4.x), w0.y);
            fma2(aij, dup2(h4.y), w1.x); fma2(afo, dup2(h4.y), w1.y);
            fma2(aij, dup2(h4.z), w2.x); fma2(afo, dup2(h4.z), w2.y);
            fma2(aij, dup2(h4.w), w3.x); fma2(afo, dup2(h4.w), w3.y);
        }

        float si, sj, sf, so;
        unpk2(aij, si, sj);
        unpk2(afo, sf, so);
        float zi = si + xi, zj = sj + xj, zf = sf + xf, zo = so + xo;

        float ig = 1.f / (1.f + expf(-zi));
        float fg = 1.f / (1.f + expf(-(zf + 1.f)));
        float og = 1.f / (1.f + expf(-zo));
        float jt = tanhf(zj);
        cst = fg * cst + ig * jt;
        float hv = og * tanhf(cst);

        *hw = hv;                               // fresh address: no stale-L1 hazard
        if (store_hs)
            hs_out[(size_t)(t * BB + b) * HH + uu] = hv;

        group_barrier(g, lt, gsense);
    }
}

// =====================================================================
// Small dense layers. transposed_in: in = g_hrd final slot (quad-packed).
// =====================================================================
__global__ void dense_kernel(const float* __restrict__ in, const float* __restrict__ W,
                             const float* __restrict__ bias, float* __restrict__ out,
                             int Kdim, int Ndim, int transposed_in, int do_relu)
{
    int gidx = blockIdx.x * blockDim.x + threadIdx.x;
    if (gidx >= BB * Ndim) return;
    int bv = gidx / Ndim;
    int j  = gidx - bv * Ndim;
    float acc = bias[j];
    if (transposed_in){
        int base = (bv >> 5) * GSZ + (bv & 31) * 4;
        for (int k = 0; k < Kdim; k++)
            acc += in[base + (k >> 2) * 128 + (k & 3)] * W[k * Ndim + j];
    } else {
        for (int k = 0; k < Kdim; k++)
            acc += in[bv * Kdim + k] * W[k * Ndim + j];
    }
    out[gidx] = do_relu ? fmaxf(acc, 0.f) : acc;
}

// =====================================================================
// Launch
// =====================================================================
#define REC_SMEM (500*16*(int)sizeof(float))   // 32000 B (weights only)

extern "C" void kernel_launch(void* const* d_in, const int* in_sizes, int n_in,
                              void* d_out, int out_size)
{
    const int*   X     = (const int*)  d_in[0];
    const float* embed = (const float*)d_in[1];
    const float* k1    = (const float*)d_in[2];
    const float* b1    = (const float*)d_in[3];
    const float* k2    = (const float*)d_in[4];
    const float* b2    = (const float*)d_in[5];
    const float* w1    = (const float*)d_in[6];
    const float* bw1   = (const float*)d_in[7];
    const float* w2    = (const float*)d_in[8];
    const float* bw2   = (const float*)d_in[9];
    const float* wp    = (const float*)d_in[10];
    const float* bp    = (const float*)d_in[11];
    float* out = (float*)d_out;

    float *xz, *hs1, *hrd, *d1, *d2;
    cudaGetSymbolAddress((void**)&xz,  g_xz);
    cudaGetSymbolAddress((void**)&hs1, g_hs1);
    cudaGetSymbolAddress((void**)&hrd, g_hrd);
    cudaGetSymbolAddress((void**)&d1,  g_d1);
    cudaGetSymbolAddress((void**)&d2,  g_d2);

    dim3 ggrid(16, 200);   // N tiles x M tiles

    // layer 1: xz1 = embed[X] @ k1[:E] + b1 ; then recurrence (stores hs1)
    sgemm_xz<1><<<ggrid, 256>>>(X, embed, k1, b1, xz);
    lstm_rec<<<NREC_BLOCKS, 256, REC_SMEM>>>(xz, k1 + (size_t)EE * G4H,
                                             hs1, 1, hrd);

    // layer 2: xz2 = hs1 @ k2[:H] + b2 ; recurrence (final h only)
    sgemm_xz<0><<<ggrid, 256>>>(nullptr, hs1, k2, b2, xz);
    lstm_rec<<<NREC_BLOCKS, 256, REC_SMEM>>>(xz, k2 + (size_t)HH * G4H,
                                             nullptr, 0, hrd);

    // head: final h of layer 2 lives in hrd slot TT (written at t=399)
    dense_kernel<<<(BB*DD1 + 255)/256, 256>>>(hrd + (size_t)TT * SLOT,
                                              w1, bw1, d1, HH,  DD1, 1, 1);
    dense_kernel<<<(BB*DD2 + 255)/256, 256>>>(d1,  w2, bw2, d2, DD1, DD2, 0, 1);
    dense_kernel<<<1, BB*CC>>>(d2, wp, bp, out, DD2, CC, 0, 0);
}

// round 11
// speedup vs baseline: 1.8088x; 1.8088x over previous
#include <cuda_runtime.h>
#include <cuda_bf16.h>
#include <math.h>

// Problem constants
#define VV   32000
#define EE   500
#define HH   500
#define DD1  800
#define DD2  100
#define CC   2
#define BB   64
#define TT   400
#define G4H  2000            // 4*H
#define MM   (BB*TT)         // 25600 rows of the big GEMM
#define NBLK 125             // 125 blocks * 4 units = 500
#define HBUF 32768           // floats per h slot (125 quads * 256, padded)

// ---------------- scratch (device globals; no allocation allowed) ----------------
__device__ float g_xz [(size_t)MM * G4H];   // 204.8 MB: xz1 from the embed GEMM
__device__ float g_h1 [2][HBUF];            // layer-1 h double buffer (quad-packed)
__device__ float g_h2 [2][HBUF];            // layer-2 h double buffer
__device__ float g_d1 [BB * DD1];
__device__ float g_d2 [BB * DD2];
__device__ unsigned g_cnt[32];              // grid barrier: counter (own 128B line)
__device__ unsigned g_sns[32];              // grid barrier: sense

// ---------------- packed f32x2 helpers ----------------
__device__ __forceinline__ unsigned long long pk2(float lo, float hi){
    unsigned long long r;
    asm("mov.b64 %0, {%1, %2};" : "=l"(r) : "f"(lo), "f"(hi));
    return r;
}
__device__ __forceinline__ unsigned long long dup2(float v){
    unsigned long long r;
    asm("mov.b64 %0, {%1, %1};" : "=l"(r) : "f"(v));
    return r;
}
__device__ __forceinline__ void fma2(unsigned long long &d,
                                     unsigned long long a,
                                     unsigned long long b){
    asm("fma.rn.f32x2 %0, %1, %2, %3;" : "=l"(d) : "l"(a), "l"(b), "l"(d));
}
__device__ __forceinline__ void unpk2(unsigned long long v, float &lo, float &hi){
    asm("mov.b64 {%0, %1}, %2;" : "=f"(lo), "=f"(hi) : "l"(v));
}

// ---------------- cp.async helpers ----------------
__device__ __forceinline__ void cp_async16(unsigned saddr, const void* gptr){
    asm volatile("cp.async.cg.shared.global [%0], [%1], 16;"
                 :: "r"(saddr), "l"(gptr) : "memory");
}
#define CP_COMMIT()  asm volatile("cp.async.commit_group;" ::: "memory")
#define CP_WAIT1()   asm volatile("cp.async.wait_group 1;" ::: "memory")
#define CP_WAIT0()   asm volatile("cp.async.wait_group 0;" ::: "memory")

// =====================================================================
// SGEMM: xz1[M=25600, 2000] = embed[X] @ k1[:E] + b1  (gather A rows)
// 128x128 block tile, BK=8, 256 threads, 8x8 per-thread tile, f32x2 math
// =====================================================================
__global__ __launch_bounds__(256)
void sgemm_xz1(const int* __restrict__ X, const float* __restrict__ A,
               const float* __restrict__ Bw, const float* __restrict__ bias,
               float* __restrict__ Cmat)
{
    __shared__ float As[8][128];
    __shared__ float Bs[8][128];

    const int tid = threadIdx.x;
    const int tx  = tid & 15;
    const int ty  = tid >> 4;
    const int m0  = blockIdx.y * 128;
    const int n0  = blockIdx.x * 128;

    const int ar  = tid >> 1;
    const int akq = (tid & 1) * 4;
    const float* arow_ptr;
    {
        int m = m0 + ar;
        int t = m >> 6, b = m & 63;
        int tok = X[b * TT + t];
        arow_ptr = A + (size_t)tok * EE;
    }
    const int bk = tid >> 5;
    const int bn = (tid & 31) * 4;

    unsigned long long acc[8][4];
    #pragma unroll
    for (int i = 0; i < 8; i++)
        #pragma unroll
        for (int j = 0; j < 4; j++) acc[i][j] = 0ULL;

    const float4 f40 = make_float4(0.f, 0.f, 0.f, 0.f);
    float4 aReg, bReg;
    {
        int k  = akq;
        aReg = (k < 500) ? *(const float4*)(arow_ptr + k) : f40;
        int kb = bk, n = n0 + bn;
        bReg = (kb < 500 && n < G4H) ? *(const float4*)(Bw + (size_t)kb * G4H + n) : f40;
    }

    const int KT = 63;
    for (int kt = 0; kt < KT; kt++){
        __syncthreads();
        As[akq+0][ar] = aReg.x; As[akq+1][ar] = aReg.y;
        As[akq+2][ar] = aReg.z; As[akq+3][ar] = aReg.w;
        *(float4*)(&Bs[bk][bn]) = bReg;
        __syncthreads();

        if (kt + 1 < KT){
            int k = (kt+1)*8 + akq;
            aReg = (k < 500) ? *(const float4*)(arow_ptr + k) : f40;
            int kb = (kt+1)*8 + bk, n = n0 + bn;
            bReg = (kb < 500 && n < G4H) ? *(const float4*)(Bw + (size_t)kb * G4H + n) : f40;
        }

        #pragma unroll
        for (int kk = 0; kk < 8; kk++){
            float4 a0 = *(const float4*)(&As[kk][ty*8]);
            float4 a1 = *(const float4*)(&As[kk][ty*8 + 4]);
            const unsigned long long* bp2 = (const unsigned long long*)(&Bs[kk][tx*8]);
            unsigned long long b0 = bp2[0], b1 = bp2[1], b2 = bp2[2], b3 = bp2[3];
            float av[8] = {a0.x,a0.y,a0.z,a0.w,a1.x,a1.y,a1.z,a1.w};
            #pragma unroll
            for (int i = 0; i < 8; i++){
                unsigned long long ad = dup2(av[i]);
                fma2(acc[i][0], ad, b0);
                fma2(acc[i][1], ad, b1);
                fma2(acc[i][2], ad, b2);
                fma2(acc[i][3], ad, b3);
            }
        }
    }

    const int nc = n0 + tx * 8;
    if (nc < G4H){
        float4 bb0 = *(const float4*)(bias + nc);
        float4 bb1 = *(const float4*)(bias + nc + 4);
        #pragma unroll
        for (int i = 0; i < 8; i++){
            int m = m0 + ty*8 + i;
            float o[8];
            unpk2(acc[i][0], o[0], o[1]);
            unpk2(acc[i][1], o[2], o[3]);
            unpk2(acc[i][2], o[4], o[5]);
            unpk2(acc[i][3], o[6], o[7]);
            float4 r0 = make_float4(o[0]+bb0.x, o[1]+bb0.y, o[2]+bb0.z, o[3]+bb0.w);
            float4 r1 = make_float4(o[4]+bb1.x, o[5]+bb1.y, o[6]+bb1.z, o[7]+bb1.w);
            float* cp = Cmat + (size_t)m * G4H + nc;
            *(float4*)(cp)     = r0;
            *(float4*)(cp + 4) = r1;
        }
    }
}

// =====================================================================
// Fused 2-layer LSTM recurrence, skewed by one step.
// 125 blocks x 512 threads, 1 block/SM (227KB smem). Block owns units
// [4*bid, 4*bid+4) of BOTH layers.
//   warps 0-7  (tid<256):  layer 1, thread=(b=tid&63, u=tid>>6), 500 MACs
//   warps 8-15 (tid>=256): layer 2, 1000 MACs (input proj from h1 + recurrent)
// Grid-step s: L1 computes h1(s) (s<TT); L2 computes h2(s-1) (s>=1).
// h exchange: quad-packed global double buffers, staged to SMEM via cp.async
// in 4 chunks (32 quads = 32KB each) double-buffered; compute overlaps staging.
// Layer-2 xz2 is computed on the fly -> no second SGEMM, no hs1 traffic.
// =====================================================================
#define WQ  8000                  // floats per weight slab
#define BUF 8192                  // floats per chunk buffer (32 quads * 256)

__global__ void lstm_fused(const float* __restrict__ xz1,
                           const float* __restrict__ k1, const float* __restrict__ k2,
                           const float* __restrict__ b2)
{
    extern __shared__ float smem[];
    float* w1h = smem;                  // [8000] layer1 hidden weights slice
    float* w2x = smem + WQ;             // [8000] layer2 input  weights slice
    float* w2h = smem + 2*WQ;           // [8000] layer2 hidden weights slice
    float* h1b[2] = { smem + 3*WQ,            smem + 3*WQ + BUF };
    float* h2b[2] = { smem + 3*WQ + 2*BUF,    smem + 3*WQ + 3*BUF };

    const int tid = threadIdx.x;
    const int lay = tid >> 8;           // 0 = layer1 threads, 1 = layer2 threads
    const int lt  = tid & 255;
    const int b   = lt & 63;            // batch
    const int u   = lt >> 6;            // unit within block slice (0..3)
    const int u0  = blockIdx.x * 4;
    const int uu  = u0 + u;

    unsigned sense = 0;
    if (tid == 0)
        asm volatile("ld.relaxed.gpu.global.u32 %0, [%1];" : "=r"(sense) : "l"(&g_sns[0]) : "memory");

    // weight slabs: w[k*16 + uw*4 + gate] = K[krow*2000 + gate*500 + u0+uw]
    for (int idx = tid; idx < 500 * 16; idx += 512){
        int k = idx >> 4, r = idx & 15;
        int uw = r >> 2, gg = r & 3;
        size_t col = (size_t)gg * HH + u0 + uw;
        w1h[idx] = k1[(size_t)(EE + k) * G4H + col];
        w2x[idx] = k2[(size_t)k        * G4H + col];
        w2h[idx] = k2[(size_t)(HH + k) * G4H + col];
    }
    // zero the t=-1 slots (slot 1 of each buffer)
    {
        int gt = blockIdx.x * 512 + tid;
        for (int i = gt; i < HBUF; i += NBLK * 512){
            g_h1[1][i] = 0.f;
            g_h2[1][i] = 0.f;
        }
    }
    // init grid barrier (weights + zeros visible everywhere)
    __syncthreads();
    if (tid == 0){
        unsigned target = sense + 1u, old;
        asm volatile("atom.acq_rel.gpu.global.add.u32 %0, [%1], %2;"
                     : "=r"(old) : "l"(&g_cnt[0]), "r"(1u) : "memory");
        if (old == (unsigned)(NBLK - 1)){
            asm volatile("st.relaxed.gpu.global.u32 [%0], %1;" :: "l"(&g_cnt[0]), "r"(0u) : "memory");
            asm volatile("st.release.gpu.global.u32 [%0], %1;" :: "l"(&g_sns[0]), "r"(target) : "memory");
        } else {
            unsigned v;
            do {
                asm volatile("ld.acquire.gpu.global.u32 %0, [%1];" : "=r"(v) : "l"(&g_sns[0]) : "memory");
            } while ((int)(v - target) < 0);
        }
        sense = target;
    }
    __syncthreads();

    const unsigned h1s[2] = { (unsigned)__cvta_generic_to_shared(h1b[0]),
                              (unsigned)__cvta_generic_to_shared(h1b[1]) };
    const unsigned h2s[2] = { (unsigned)__cvta_generic_to_shared(h2b[0]),
                              (unsigned)__cvta_generic_to_shared(h2b[1]) };

    float cst = 0.f;                                   // c-state (per layer thread)
    const int hq  = (uu >> 2) * 256 + b * 4 + (uu & 3); // quad-packed h offset
    const int b4  = b * 4;
    const float* xzb = xz1 + (size_t)b * G4H + uu;      // layer1 xz base

    // layer-2 gate biases (b2 is zeros per spec, honor anyway)
    float g2i = 0.f, g2j = 0.f, g2f = 0.f, g2o = 0.f;
    if (lay == 1){
        g2i = b2[uu]; g2j = b2[uu + 500]; g2f = b2[uu + 1000]; g2o = b2[uu + 1500];
    }

    for (int s = 0; s <= TT; s++){
        const float4* src1 = (const float4*)g_h1[(s + 1) & 1];   // h1(s-1)
        const float4* src2 = (const float4*)g_h2[s & 1];         // h2(s-2)

        // prologue: stage chunks 0 and 1 (each = h1 32KB + h2 32KB)
        #pragma unroll
        for (int c = 0; c < 2; c++){
            for (int idx = tid; idx < 2048; idx += 512){
                cp_async16(h1s[c] + idx * 16, src1 + c * 2048 + idx);
                cp_async16(h2s[c] + idx * 16, src2 + c * 2048 + idx);
            }
            CP_COMMIT();
        }

        // layer-1 xz loads (fly during staging/compute)
        float xi = 0.f, xj = 0.f, xf = 0.f, xo = 0.f;
        if (lay == 0 && s < TT){
            size_t mrow = (size_t)s * BB * G4H;
            xi = __ldcs(xzb + mrow);
            xj = __ldcs(xzb + mrow + 500);
            xf = __ldcs(xzb + mrow + 1000);
            xo = __ldcs(xzb + mrow + 1500);
        }

        unsigned long long aij, afo;
        if (lay == 0){ aij = pk2(xi, xj);   afo = pk2(xf, xo);  }
        else         { aij = pk2(g2i, g2j); afo = pk2(g2f, g2o);}

        // 4 chunk phases: wait chunk c, compute, re-stage chunk c+2
        #pragma unroll
        for (int c = 0; c < 4; c++){
            if (c < 3) { CP_WAIT1(); } else { CP_WAIT0(); }
            __syncthreads();                       // chunk c visible to all

            const int q0 = c * 32;
            const int nq = (c < 3) ? 32 : 29;      // 125 quads total
            float* hb1 = h1b[c & 1];
            float* hb2 = h2b[c & 1];

            if (lay == 0){
                if (s < TT){
                    #pragma unroll 4
                    for (int ql = 0; ql < 32; ql++){
                        if (ql >= nq) break;
                        float4 h4 = *(const float4*)(hb1 + ql * 256 + b4);
                        const float* wq = w1h + (q0 + ql) * 64 + u * 4;
                        ulonglong2 w0 = *(const ulonglong2*)(wq);
                        ulonglong2 w1 = *(const ulonglong2*)(wq + 16);
                        ulonglong2 w2 = *(const ulonglong2*)(wq + 32);
                        ulonglong2 w3 = *(const ulonglong2*)(wq + 48);
                        fma2(aij, dup2(h4.x), w0.x); fma2(afo, dup2(h4.x), w0.y);
                        fma2(aij, dup2(h4.y), w1.x); fma2(afo, dup2(h4.y), w1.y);
                        fma2(aij, dup2(h4.z), w2.x); fma2(afo, dup2(h4.z), w2.y);
                        fma2(aij, dup2(h4.w), w3.x); fma2(afo, dup2(h4.w), w3.y);
                    }
                }
            } else {
                if (s >= 1){
                    #pragma unroll 2
                    for (int ql = 0; ql < 32; ql++){
                        if (ql >= nq) break;
                        float4 x4 = *(const float4*)(hb1 + ql * 256 + b4);  // h1(s-1)
                        float4 h4 = *(const float4*)(hb2 + ql * 256 + b4);  // h2(s-2)
                        const float* wx = w2x + (q0 + ql) * 64 + u * 4;
                        const float* wh = w2h + (q0 + ql) * 64 + u * 4;
                        ulonglong2 x0 = *(const ulonglong2*)(wx);
                        ulonglong2 x1 = *(const ulonglong2*)(wx + 16);
                        ulonglong2 x2 = *(const ulonglong2*)(wx + 32);
                        ulonglong2 x3 = *(const ulonglong2*)(wx + 48);
                        fma2(aij, dup2(x4.x), x0.x); fma2(afo, dup2(x4.x), x0.y);
                        fma2(aij, dup2(x4.y), x1.x); fma2(afo, dup2(x4.y), x1.y);
                        fma2(aij, dup2(x4.z), x2.x); fma2(afo, dup2(x4.z), x2.y);
                        fma2(aij, dup2(x4.w), x3.x); fma2(afo, dup2(x4.w), x3.y);
                        ulonglong2 w0 = *(const ulonglong2*)(wh);
                        ulonglong2 w1 = *(const ulonglong2*)(wh + 16);
                        ulonglong2 w2 = *(const ulonglong2*)(wh + 32);
                        ulonglong2 w3 = *(const ulonglong2*)(wh + 48);
                        fma2(aij, dup2(h4.x), w0.x); fma2(afo, dup2(h4.x), w0.y);
                        fma2(aij, dup2(h4.y), w1.x); fma2(afo, dup2(h4.y), w1.y);
                        fma2(aij, dup2(h4.z), w2.x); fma2(afo, dup2(h4.z), w2.y);
                        fma2(aij, dup2(h4.w), w3.x); fma2(afo, dup2(h4.w), w3.y);
                    }
                }
            }

            __syncthreads();                       // everyone done reading chunk c
            if (c < 2){                            // re-stage chunk c+2 into buf[c&1]
                int cn = c + 2;
                int cnt = (cn < 3) ? 2048 : 29 * 64;
                for (int idx = tid; idx < cnt; idx += 512){
                    cp_async16(h1s[c & 1] + idx * 16, src1 + cn * 2048 + idx);
                    cp_async16(h2s[c & 1] + idx * 16, src2 + cn * 2048 + idx);
                }
                CP_COMMIT();
            }
        }

        // gates + state update + h write
        bool active = (lay == 0) ? (s < TT) : (s >= 1);
        if (active){
            float si, sj, sf, so;
            unpk2(aij, si, sj);
            unpk2(afo, sf, so);
            float ig = 1.f / (1.f + expf(-si));
            float fg = 1.f / (1.f + expf(-(sf + 1.f)));
            float og = 1.f / (1.f + expf(-so));
            float jt = tanhf(sj);
            cst = fg * cst + ig * jt;
            float hv = og * tanhf(cst);
            if (lay == 0) __stcg(&g_h1[s & 1][hq], hv);          // h1(s)
            else          __stcg(&g_h2[(s + 1) & 1][hq], hv);    // h2(s-1)
        }

        // grid barrier (orders the h stores before the release arrive)
        __syncthreads();
        if (tid == 0){
            unsigned target = sense + 1u, old;
            asm volatile("atom.acq_rel.gpu.global.add.u32 %0, [%1], %2;"
                         : "=r"(old) : "l"(&g_cnt[0]), "r"(1u) : "memory");
            if (old == (unsigned)(NBLK - 1)){
                asm volatile("st.relaxed.gpu.global.u32 [%0], %1;" :: "l"(&g_cnt[0]), "r"(0u) : "memory");
                asm volatile("st.release.gpu.global.u32 [%0], %1;" :: "l"(&g_sns[0]), "r"(target) : "memory");
            } else {
                unsigned v;
                do {
                    asm volatile("ld.acquire.gpu.global.u32 %0, [%1];" : "=r"(v) : "l"(&g_sns[0]) : "memory");
                } while ((int)(v - target) < 0);
            }
            sense = target;
        }
        __syncthreads();
    }
}

// =====================================================================
// Small dense layers. transposed_in: in = quad-packed h layout (64 batches).
// =====================================================================
__global__ void dense_kernel(const float* __restrict__ in, const float* __restrict__ W,
                             const float* __restrict__ bias, float* __restrict__ out,
                             int Kdim, int Ndim, int transposed_in, int do_relu)
{
    int gidx = blockIdx.x * blockDim.x + threadIdx.x;
    if (gidx >= BB * Ndim) return;
    int bv = gidx / Ndim;
    int j  = gidx - bv * Ndim;
    float acc = bias[j];
    if (transposed_in){
        for (int k = 0; k < Kdim; k++)
            acc += in[(k >> 2) * 256 + bv * 4 + (k & 3)] * W[k * Ndim + j];
    } else {
        for (int k = 0; k < Kdim; k++)
            acc += in[bv * Kdim + k] * W[k * Ndim + j];
    }
    out[gidx] = do_relu ? fmaxf(acc, 0.f) : acc;
}

// =====================================================================
// Launch
// =====================================================================
#define FUSED_SMEM ((3*WQ + 4*BUF) * (int)sizeof(float))   // 227072 B

extern "C" void kernel_launch(void* const* d_in, const int* in_sizes, int n_in,
                              void* d_out, int out_size)
{
    const int*   X     = (const int*)  d_in[0];
    const float* embed = (const float*)d_in[1];
    const float* k1    = (const float*)d_in[2];
    const float* b1    = (const float*)d_in[3];
    const float* k2    = (const float*)d_in[4];
    const float* b2    = (const float*)d_in[5];
    const float* w1    = (const float*)d_in[6];
    const float* bw1   = (const float*)d_in[7];
    const float* w2    = (const float*)d_in[8];
    const float* bw2   = (const float*)d_in[9];
    const float* wp    = (const float*)d_in[10];
    const float* bp    = (const float*)d_in[11];
    float* out = (float*)d_out;

    float *xz, *h2fin, *d1, *d2;
    cudaGetSymbolAddress((void**)&xz,    g_xz);
    cudaGetSymbolAddress((void**)&h2fin, g_h2);   // g_h2[0]; final h2 is slot 1
    cudaGetSymbolAddress((void**)&d1,    g_d1);
    cudaGetSymbolAddress((void**)&d2,    g_d2);

    cudaFuncSetAttribute(lstm_fused, cudaFuncAttributeMaxDynamicSharedMemorySize, FUSED_SMEM);

    // xz1 = embed[X] @ k1[:E] + b1
    dim3 ggrid(16, 200);
    sgemm_xz1<<<ggrid, 256>>>(X, embed, k1, b1, xz);

    // fused skewed 2-layer recurrence (computes everything up to final h2)
    lstm_fused<<<NBLK, 512, FUSED_SMEM>>>(xz, k1, k2, b2);

    // head: h2(TT-1) was written at grid-step s=TT to slot (TT+1)&1 = 1
    const float* h2last = h2fin + HBUF;   // g_h2[1]
    dense_kernel<<<(BB*DD1 + 255)/256, 256>>>(h2last, w1, bw1, d1, HH,  DD1, 1, 1);
    dense_kernel<<<(BB*DD2 + 255)/256, 256>>>(d1,  w2, bw2, d2, DD1, DD2, 0, 1);
    dense_kernel<<<1, BB*CC>>>(d2, wp, bp, out, DD2, CC, 0, 0);
}

// round 14
// speedup vs baseline: 1.8176x; 1.0049x over previous
#include <cuda_runtime.h>
#include <cuda_bf16.h>
#include <math.h>

// Problem constants
#define VV   32000
#define EE   500
#define HH   500
#define DD1  800
#define DD2  100
#define CC   2
#define BB   64
#define TT   400
#define G4H  2000            // 4*H
#define MM   (BB*TT)         // 25600 rows of the big GEMMs
#define NREC_BLOCKS 125      // 125 * 4 units = 500
#define GSZ  16384           // floats per group slice (256 pairs x 64) = 64KB
#define TMA_SPIN_CAP 4096    // bounded wait: legit completion is ~10-100 iters

// ---------------- scratch (device globals; no allocation allowed) ----------------
__device__ float g_xz [(size_t)MM * G4H];              // 204.8 MB, reused for both layers
__device__ float g_hs1[(size_t)MM * HH];               // 51.2 MB
__device__ __align__(128) float g_hb0[2 * GSZ];        // [group][slice]
__device__ __align__(128) float g_hb1[2 * GSZ];
__device__ float g_d1 [BB * DD1];
__device__ float g_d2 [BB * DD2];
// barrier state: counter and sense on separate 128B lines, per group
__device__ unsigned g_gcnt[2][32];
__device__ unsigned g_gsns[2][32];
__device__ unsigned g_icnt[32];
__device__ unsigned g_isns[32];

// ---------------- packed f32x2 helpers ----------------
__device__ __forceinline__ unsigned long long pk2(float lo, float hi){
    unsigned long long r;
    asm("mov.b64 %0, {%1, %2};" : "=l"(r) : "f"(lo), "f"(hi));
    return r;
}
__device__ __forceinline__ unsigned long long dup2(float v){
    unsigned long long r;
    asm("mov.b64 %0, {%1, %1};" : "=l"(r) : "f"(v));
    return r;
}
__device__ __forceinline__ void fma2(unsigned long long &d,
                                     unsigned long long a,
                                     unsigned long long b){
    asm("fma.rn.f32x2 %0, %1, %2, %3;" : "=l"(d) : "l"(a), "l"(b), "l"(d));
}
__device__ __forceinline__ void unpk2(unsigned long long v, float &lo, float &hi){
    asm("mov.b64 {%0, %1}, %2;" : "=f"(lo), "=f"(hi) : "l"(v));
}

// ---------------- cp.async helpers (fallback staging path) ----------------
__device__ __forceinline__ void cp_async16(unsigned saddr, const void* gptr){
    asm volatile("cp.async.cg.shared.global [%0], [%1], 16;"
                 :: "r"(saddr), "l"(gptr) : "memory");
}
#define CP_COMMIT()  asm volatile("cp.async.commit_group;" ::: "memory")
#define CP_WAIT0()   asm volatile("cp.async.wait_group 0;" ::: "memory")

// =====================================================================
// SGEMM: C[M=25600, N=2000] = A[M,500] @ Bw[500,2000] + bias
// GATHER=1: A row m -> embed[X[b*T+t]] with m = t*64+b
// =====================================================================
template<int GATHER>
__global__ __launch_bounds__(256)
void sgemm_xz(const int* __restrict__ X, const float* __restrict__ A,
              const float* __restrict__ Bw, const float* __restrict__ bias,
              float* __restrict__ Cmat)
{
    __shared__ float As[8][128];
    __shared__ float Bs[8][128];

    const int tid = threadIdx.x;
    const int tx  = tid & 15;
    const int ty  = tid >> 4;
    const int m0  = blockIdx.y * 128;
    const int n0  = blockIdx.x * 128;

    const int ar  = tid >> 1;
    const int akq = (tid & 1) * 4;
    const float* arow_ptr;
    {
        int m = m0 + ar;
        if (GATHER){
            int t = m >> 6, b = m & 63;
            int tok = X[b * TT + t];
            arow_ptr = A + (size_t)tok * EE;
        } else {
            arow_ptr = A + (size_t)m * HH;
        }
    }
    const int bk = tid >> 5;
    const int bn = (tid & 31) * 4;

    unsigned long long acc[8][4];
    #pragma unroll
    for (int i = 0; i < 8; i++)
        #pragma unroll
        for (int j = 0; j < 4; j++) acc[i][j] = 0ULL;

    const float4 f40 = make_float4(0.f, 0.f, 0.f, 0.f);
    float4 aReg, bReg;
    {
        int k  = akq;
        aReg = (k < 500) ? *(const float4*)(arow_ptr + k) : f40;
        int kb = bk, n = n0 + bn;
        bReg = (kb < 500 && n < G4H) ? *(const float4*)(Bw + (size_t)kb * G4H + n) : f40;
    }

    const int KT = 63;
    for (int kt = 0; kt < KT; kt++){
        __syncthreads();
        As[akq+0][ar] = aReg.x; As[akq+1][ar] = aReg.y;
        As[akq+2][ar] = aReg.z; As[akq+3][ar] = aReg.w;
        *(float4*)(&Bs[bk][bn]) = bReg;
        __syncthreads();

        if (kt + 1 < KT){
            int k = (kt+1)*8 + akq;
            aReg = (k < 500) ? *(const float4*)(arow_ptr + k) : f40;
            int kb = (kt+1)*8 + bk, n = n0 + bn;
            bReg = (kb < 500 && n < G4H) ? *(const float4*)(Bw + (size_t)kb * G4H + n) : f40;
        }

        #pragma unroll
        for (int kk = 0; kk < 8; kk++){
            float4 a0 = *(const float4*)(&As[kk][ty*8]);
            float4 a1 = *(const float4*)(&As[kk][ty*8 + 4]);
            const unsigned long long* bp2 = (const unsigned long long*)(&Bs[kk][tx*8]);
            unsigned long long b0 = bp2[0], b1 = bp2[1], b2 = bp2[2], b3 = bp2[3];
            float av[8] = {a0.x,a0.y,a0.z,a0.w,a1.x,a1.y,a1.z,a1.w};
            #pragma unroll
            for (int i = 0; i < 8; i++){
                unsigned long long ad = dup2(av[i]);
                fma2(acc[i][0], ad, b0);
                fma2(acc[i][1], ad, b1);
                fma2(acc[i][2], ad, b2);
                fma2(acc[i][3], ad, b3);
            }
        }
    }

    const int nc = n0 + tx * 8;
    if (nc < G4H){
        float4 bb0 = *(const float4*)(bias + nc);
        float4 bb1 = *(const float4*)(bias + nc + 4);
        #pragma unroll
        for (int i = 0; i < 8; i++){
            int m = m0 + ty*8 + i;
            float o[8];
            unpk2(acc[i][0], o[0], o[1]);
            unpk2(acc[i][1], o[2], o[3]);
            unpk2(acc[i][2], o[4], o[5]);
            unpk2(acc[i][3], o[6], o[7]);
            float4 r0 = make_float4(o[0]+bb0.x, o[1]+bb0.y, o[2]+bb0.z, o[3]+bb0.w);
            float4 r1 = make_float4(o[4]+bb1.x, o[5]+bb1.y, o[6]+bb1.z, o[7]+bb1.w);
            float* cp = Cmat + (size_t)m * G4H + nc;
            *(float4*)(cp)     = r0;
            *(float4*)(cp + 4) = r1;
        }
    }
}

// =====================================================================
// Per-group flat grid barrier (R6, proven). bar.sync orders the group's weak
// stores before lt0's gpu-scope acq_rel arrive; pollers acquire-load the sense.
// =====================================================================
__device__ __forceinline__ void group_barrier(int g, int lt, unsigned &sense)
{
    asm volatile("bar.sync %0, 128;" :: "r"(3 + g) : "memory");
    if (lt == 0){
        unsigned target = sense + 1u;
        unsigned old;
        asm volatile("atom.acq_rel.gpu.global.add.u32 %0, [%1], %2;"
                     : "=r"(old) : "l"(&g_gcnt[g][0]), "r"(1u) : "memory");
        if (old == (unsigned)(NREC_BLOCKS - 1)){
            asm volatile("st.relaxed.gpu.global.u32 [%0], %1;"
                         :: "l"(&g_gcnt[g][0]), "r"(0u) : "memory");
            asm volatile("st.release.gpu.global.u32 [%0], %1;"
                         :: "l"(&g_gsns[g][0]), "r"(target) : "memory");
        } else {
            unsigned v;
            do {
                asm volatile("ld.acquire.gpu.global.u32 %0, [%1];"
                             : "=r"(v) : "l"(&g_gsns[g][0]) : "memory");
            } while ((int)(v - target) < 0);
        }
        sense = target;
    }
    asm volatile("bar.sync %0, 128;" :: "r"(3 + g) : "memory");
}

// =====================================================================
// Persistent LSTM recurrence, two independent batch-groups per SM.
// 125 blocks x 256 threads, 1 block/SM. Group g = threads [g*128, g*128+128):
// 32 batches x 4 units. Per-group grid barrier + 64KB h slice.
// h slice layout: h[g][(k>>1)*64 + (b&31)*2 + (k&1)], pairs padded to 256.
// h staging, primary path: ONE TMA bulk copy (64KB) per group per step,
// issued by lt==0, completion via per-group mbarrier. Removes the ~16K
// cyc/SM/step LDGSTS issue cost that dominated R6-R11.
// HANG-PROOF: lt0's mbarrier wait is bounded (TMA_SPIN_CAP). On timeout the
// group permanently falls back to per-thread cp.async staging (R6 path);
// late TMA data rewrites identical bytes (benign), mbarrier never reused.
// =====================================================================
__global__ void lstm_rec(const float* __restrict__ xz, const float* __restrict__ Wh,
                         float* __restrict__ hs_out, int store_hs,
                         float* __restrict__ hb0, float* __restrict__ hb1)
{
    extern __shared__ float smem[];
    float* hsm = smem;                          // 2 * 16384 floats (128 KB)
    float* wsm = smem + 2 * GSZ;                // 8000 floats (32 KB)
    // mbarriers + status flags after weights (offset 163072, 8B aligned)
    unsigned long long* mbars = (unsigned long long*)(smem + 2 * GSZ + 8000);
    volatile unsigned* s_ok   = (volatile unsigned*)(mbars + 2);   // [2]

    const int tid = threadIdx.x;
    const int g   = tid >> 7;          // batch group 0/1
    const int lt  = tid & 127;         // lane within group
    const int bl  = lt & 31;           // batch within group
    const int u   = (lt >> 5) & 3;     // unit within block slice
    const int u0  = blockIdx.x * 4;
    const int uu  = u0 + u;
    const int b   = g * 32 + bl;       // global batch

    const unsigned mbar_g = (unsigned)__cvta_generic_to_shared(&mbars[g]);

    unsigned gsense = 0, isense = 0;
    if (lt == 0)
        asm volatile("ld.relaxed.gpu.global.u32 %0, [%1];" : "=r"(gsense) : "l"(&g_gsns[g][0]) : "memory");
    if (tid == 0)
        asm volatile("ld.relaxed.gpu.global.u32 %0, [%1];" : "=r"(isense) : "l"(&g_isns[0]) : "memory");

    // init the two mbarriers (arrive count 1: the expect_tx arrival)
    if (tid == 0){
        asm volatile("mbarrier.init.shared.b64 [%0], %1;"
                     :: "r"((unsigned)__cvta_generic_to_shared(&mbars[0])), "r"(1u) : "memory");
        asm volatile("mbarrier.init.shared.b64 [%0], %1;"
                     :: "r"((unsigned)__cvta_generic_to_shared(&mbars[1])), "r"(1u) : "memory");
    }

    // cache weight slice: wsm[k*16 + uw*4 + gate] = Wh[k*2000 + gate*500 + u0+uw]
    for (int idx = tid; idx < 500 * 16; idx += 256){
        int k = idx >> 4, r = idx & 15;
        int uw = r >> 2, gg = r & 3;
        wsm[idx] = Wh[(size_t)k * G4H + gg * HH + u0 + uw];
    }
    // zero both h buffers (incl. pad pairs, stay zero forever)
    {
        int gt = blockIdx.x * 256 + tid;
        float4 z4 = make_float4(0.f, 0.f, 0.f, 0.f);
        for (int i = gt; i < (2 * GSZ) / 4; i += NREC_BLOCKS * 256){
            ((float4*)hb0)[i] = z4;
            ((float4*)hb1)[i] = z4;
        }
    }
    // init: full-grid barrier (both groups) so weights/zeros/mbarriers are ready
    __syncthreads();
    if (tid == 0){
        unsigned target = isense + 1u, old;
        asm volatile("atom.acq_rel.gpu.global.add.u32 %0, [%1], %2;"
                     : "=r"(old) : "l"(&g_icnt[0]), "r"(1u) : "memory");
        if (old == (unsigned)(NREC_BLOCKS - 1)){
            asm volatile("st.relaxed.gpu.global.u32 [%0], %1;" :: "l"(&g_icnt[0]), "r"(0u) : "memory");
            asm volatile("st.release.gpu.global.u32 [%0], %1;" :: "l"(&g_isns[0]), "r"(target) : "memory");
        } else {
            unsigned v;
            do {
                asm volatile("ld.acquire.gpu.global.u32 %0, [%1];" : "=r"(v) : "l"(&g_isns[0]) : "memory");
            } while ((int)(v - target) < 0);
        }
    }
    __syncthreads();

    float* hsg = hsm + g * GSZ;
    const unsigned hsg_s = (unsigned)__cvta_generic_to_shared(hsg);
    float cst = 0.f;
    const int hoff = g * GSZ + (uu >> 1) * 64 + bl * 2 + (uu & 1);
    const float* xzb = xz + (size_t)b * G4H + uu;
    unsigned ph = 0;                    // mbarrier phase parity
    bool use_tma = true;                // flips off permanently on first timeout

    for (int t = 0; t < TT; t++){
        const float* hprev = ((t & 1) ? hb1 : hb0) + g * GSZ;
        float*       hnext = ((t & 1) ? hb0 : hb1);

        // primary path: issue ONE TMA bulk copy for this group's 64KB slice
        if (use_tma && lt == 0){
            asm volatile("fence.proxy.async;" ::: "memory");
            asm volatile("mbarrier.arrive.expect_tx.shared.b64 _, [%0], %1;"
                         :: "r"(mbar_g), "r"(65536u) : "memory");
            asm volatile("cp.async.bulk.shared::cluster.global.mbarrier::complete_tx::bytes "
                         "[%0], [%1], %2, [%3];"
                         :: "r"(hsg_s), "l"(hprev), "r"(65536u), "r"(mbar_g) : "memory");
        }

        // xz loads (DRAM) fly during the transfer; added at the END (off chain)
        size_t mrow = (size_t)t * BB * G4H;
        float xi = __ldcs(xzb + mrow);
        float xj = __ldcs(xzb + mrow + 500);
        float xf = __ldcs(xzb + mrow + 1000);
        float xo = __ldcs(xzb + mrow + 1500);

        bool staged = false;
        if (use_tma){
            // lt0 waits with a bounded spin; result published via shared flag
            if (lt == 0){
                unsigned done = 0;
                int it = 0;
                do {
                    asm volatile(
                        "{\n\t.reg .pred p;\n\t"
                        "mbarrier.try_wait.parity.acquire.cta.shared::cta.b64 p, [%1], %2;\n\t"
                        "selp.b32 %0, 1, 0, p;\n\t}"
                        : "=r"(done) : "r"(mbar_g), "r"(ph) : "memory");
                } while (!done && ++it < TMA_SPIN_CAP);
                s_ok[g] = done;
            }
            asm volatile("bar.sync %0, 128;" :: "r"(3 + g) : "memory");
            if (s_ok[g]){
                ph ^= 1u;
                staged = true;
            } else {
                use_tma = false;        // permanent fallback for this group
            }
        }
        if (!staged){
            // fallback: per-thread cp.async staging (R6 path, proven)
            #pragma unroll
            for (int i = 0; i < 32; i++){
                int idx = lt + i * 128;
                cp_async16(hsg_s + idx * 16, (const float4*)hprev + idx);
            }
            CP_COMMIT();
            CP_WAIT0();
            asm volatile("bar.sync %0, 128;" :: "r"(3 + g) : "memory");
        }

        unsigned long long aij = 0ULL, afo = 0ULL;
        #pragma unroll 5
        for (int p = 0; p < 250; p++){
            float2 h2 = *(const float2*)(hsg + p * 64 + bl * 2);
            ulonglong2 wa = *(const ulonglong2*)(wsm + ((2*p    ) * 4 + u) * 4);
            ulonglong2 wb = *(const ulonglong2*)(wsm + ((2*p + 1) * 4 + u) * 4);
            unsigned long long h0 = dup2(h2.x), h1 = dup2(h2.y);
            fma2(aij, h0, wa.x); fma2(afo, h0, wa.y);
            fma2(aij, h1, wb.x); fma2(afo, h1, wb.y);
        }

        float si, sj, sf, so;
        unpk2(aij, si, sj);
        unpk2(afo, sf, so);
        float zi = si + xi, zj = sj + xj, zf = sf + xf, zo = so + xo;

        float ig = 1.f / (1.f + expf(-zi));
        float fg = 1.f / (1.f + expf(-(zf + 1.f)));
        float og = 1.f / (1.f + expf(-zo));
        float jt = tanhf(zj);
        cst = fg * cst + ig * jt;
        float hv = og * tanhf(cst);

        __stcg(hnext + hoff, hv);
        if (store_hs)
            hs_out[(size_t)(t * BB + b) * HH + uu] = hv;

        group_barrier(g, lt, gsense);
    }
}

// =====================================================================
// Small dense layers. transposed_in: in uses the grouped pair-packed h layout.
// =====================================================================
__global__ void dense_kernel(const float* __restrict__ in, const float* __restrict__ W,
                             const float* __restrict__ bias, float* __restrict__ out,
                             int Kdim, int Ndim, int transposed_in, int do_relu)
{
    int gidx = blockIdx.x * blockDim.x + threadIdx.x;
    if (gidx >= BB * Ndim) return;
    int bv = gidx / Ndim;
    int j  = gidx - bv * Ndim;
    float acc = bias[j];
    if (transposed_in){
        int base = (bv >> 5) * GSZ + (bv & 31) * 2;
        #pragma unroll 8
        for (int k = 0; k < Kdim; k++)
            acc += in[base + (k >> 1) * 64 + (k & 1)] * W[k * Ndim + j];
    } else {
        #pragma unroll 8
        for (int k = 0; k < Kdim; k++)
            acc += in[bv * Kdim + k] * W[k * Ndim + j];
    }
    out[gidx] = do_relu ? fmaxf(acc, 0.f) : acc;
}

// =====================================================================
// Launch
// =====================================================================
#define REC_SMEM ((2*GSZ + 8000) * (int)sizeof(float) + 64)   // 163136 B

extern "C" void kernel_launch(void* const* d_in, const int* in_sizes, int n_in,
                              void* d_out, int out_size)
{
    const int*   X     = (const int*)  d_in[0];
    const float* embed = (const float*)d_in[1];
    const float* k1    = (const float*)d_in[2];
    const float* b1    = (const float*)d_in[3];
    const float* k2    = (const float*)d_in[4];
    const float* b2    = (const float*)d_in[5];
    const float* w1    = (const float*)d_in[6];
    const float* bw1   = (const float*)d_in[7];
    const float* w2    = (const float*)d_in[8];
    const float* bw2   = (const float*)d_in[9];
    const float* wp    = (const float*)d_in[10];
    const float* bp    = (const float*)d_in[11];
    float* out = (float*)d_out;

    float *xz, *hs1, *hb0, *hb1, *d1, *d2;
    cudaGetSymbolAddress((void**)&xz,  g_xz);
    cudaGetSymbolAddress((void**)&hs1, g_hs1);
    cudaGetSymbolAddress((void**)&hb0, g_hb0);
    cudaGetSymbolAddress((void**)&hb1, g_hb1);
    cudaGetSymbolAddress((void**)&d1,  g_d1);
    cudaGetSymbolAddress((void**)&d2,  g_d2);

    cudaFuncSetAttribute(lstm_rec, cudaFuncAttributeMaxDynamicSharedMemorySize, REC_SMEM);

    dim3 ggrid(16, 200);   // N tiles x M tiles

    // layer 1: xz1 = embed[X] @ k1[:E] + b1 ; then recurrence (stores hs1)
    sgemm_xz<1><<<ggrid, 256>>>(X, embed, k1, b1, xz);
    lstm_rec<<<NREC_BLOCKS, 256, REC_SMEM>>>(xz, k1 + (size_t)EE * G4H,
                                             hs1, 1, hb0, hb1);

    // layer 2: xz2 = hs1 @ k2[:H] + b2 ; recurrence (final h only)
    sgemm_xz<0><<<ggrid, 256>>>(nullptr, hs1, k2, b2, xz);
    lstm_rec<<<NREC_BLOCKS, 256, REC_SMEM>>>(xz, k2 + (size_t)HH * G4H,
                                             nullptr, 0, hb0, hb1);

    // head: T=400 even -> final h in hb0 (written at t=399)
    dense_kernel<<<(BB*DD1 + 255)/256, 256>>>(hb0, w1, bw1, d1, HH,  DD1, 1, 1);
    dense_kernel<<<(BB*DD2 + 255)/256, 256>>>(d1,  w2, bw2, d2, DD1, DD2, 0, 1);
    dense_kernel<<<1, BB*CC>>>(d2, wp, bp, out, DD2, CC, 0, 0);
}

// round 15
// speedup vs baseline: 1.9845x; 1.0919x over previous
#include <cuda_runtime.h>
#include <cuda_bf16.h>
#include <cuda_fp16.h>
#include <math.h>

// Problem constants
#define VV   32000
#define EE   500
#define HH   500
#define DD1  800
#define DD2  100
#define CC   2
#define BB   64
#define TT   400
#define G4H  2000            // 4*H
#define MM   (BB*TT)         // 25600 rows of the big GEMMs
#define NREC_BLOCKS 125      // 125 * 4 units = 500
#define GSZH 16384           // halves per group slice (128 quads x 32b x 4) = 32KB
#define TMA_SPIN_CAP 65536   // bounded per-step wait (hang-proof)
#define PROBE_SPIN   16384   // bounded probe wait at init

// ---------------- scratch (device globals; no allocation allowed) ----------------
__device__ float  g_xz [(size_t)MM * G4H];             // 204.8 MB, reused for both layers
__device__ float  g_hs1[(size_t)MM * HH];              // 51.2 MB
__device__ __align__(128) __half g_hb0[2 * GSZH];      // [group][slice], fp16 h exchange
__device__ __align__(128) __half g_hb1[2 * GSZH];
__device__ float  g_d1 [BB * DD1];
__device__ float  g_d2 [BB * DD2];
// barrier state: counter and sense on separate 128B lines, per group
__device__ unsigned g_gcnt[2][32];
__device__ unsigned g_gsns[2][32];
__device__ unsigned g_icnt[32];
__device__ unsigned g_isns[32];

// ---------------- packed f32x2 helpers ----------------
__device__ __forceinline__ unsigned long long pk2(float lo, float hi){
    unsigned long long r;
    asm("mov.b64 %0, {%1, %2};" : "=l"(r) : "f"(lo), "f"(hi));
    return r;
}
__device__ __forceinline__ unsigned long long dup2(float v){
    unsigned long long r;
    asm("mov.b64 %0, {%1, %1};" : "=l"(r) : "f"(v));
    return r;
}
__device__ __forceinline__ void fma2(unsigned long long &d,
                                     unsigned long long a,
                                     unsigned long long b){
    asm("fma.rn.f32x2 %0, %1, %2, %3;" : "=l"(d) : "l"(a), "l"(b), "l"(d));
}
__device__ __forceinline__ void unpk2(unsigned long long v, float &lo, float &hi){
    asm("mov.b64 {%0, %1}, %2;" : "=f"(lo), "=f"(hi) : "l"(v));
}

// ---------------- cp.async helpers (fallback staging path) ----------------
__device__ __forceinline__ void cp_async16(unsigned saddr, const void* gptr){
    asm volatile("cp.async.cg.shared.global [%0], [%1], 16;"
                 :: "r"(saddr), "l"(gptr) : "memory");
}
#define CP_COMMIT()  asm volatile("cp.async.commit_group;" ::: "memory")
#define CP_WAIT0()   asm volatile("cp.async.wait_group 0;" ::: "memory")

// =====================================================================
// SGEMM: C[M=25600, N=2000] = A[M,500] @ Bw[500,2000] + bias
// GATHER=1: A row m -> embed[X[b*T+t]] with m = t*64+b
// =====================================================================
template<int GATHER>
__global__ __launch_bounds__(256)
void sgemm_xz(const int* __restrict__ X, const float* __restrict__ A,
              const float* __restrict__ Bw, const float* __restrict__ bias,
              float* __restrict__ Cmat)
{
    __shared__ float As[8][128];
    __shared__ float Bs[8][128];

    const int tid = threadIdx.x;
    const int tx  = tid & 15;
    const int ty  = tid >> 4;
    const int m0  = blockIdx.y * 128;
    const int n0  = blockIdx.x * 128;

    const int ar  = tid >> 1;
    const int akq = (tid & 1) * 4;
    const float* arow_ptr;
    {
        int m = m0 + ar;
        if (GATHER){
            int t = m >> 6, b = m & 63;
            int tok = X[b * TT + t];
            arow_ptr = A + (size_t)tok * EE;
        } else {
            arow_ptr = A + (size_t)m * HH;
        }
    }
    const int bk = tid >> 5;
    const int bn = (tid & 31) * 4;

    unsigned long long acc[8][4];
    #pragma unroll
    for (int i = 0; i < 8; i++)
        #pragma unroll
        for (int j = 0; j < 4; j++) acc[i][j] = 0ULL;

    const float4 f40 = make_float4(0.f, 0.f, 0.f, 0.f);
    float4 aReg, bReg;
    {
        int k  = akq;
        aReg = (k < 500) ? *(const float4*)(arow_ptr + k) : f40;
        int kb = bk, n = n0 + bn;
        bReg = (kb < 500 && n < G4H) ? *(const float4*)(Bw + (size_t)kb * G4H + n) : f40;
    }

    const int KT = 63;
    for (int kt = 0; kt < KT; kt++){
        __syncthreads();
        As[akq+0][ar] = aReg.x; As[akq+1][ar] = aReg.y;
        As[akq+2][ar] = aReg.z; As[akq+3][ar] = aReg.w;
        *(float4*)(&Bs[bk][bn]) = bReg;
        __syncthreads();

        if (kt + 1 < KT){
            int k = (kt+1)*8 + akq;
            aReg = (k < 500) ? *(const float4*)(arow_ptr + k) : f40;
            int kb = (kt+1)*8 + bk, n = n0 + bn;
            bReg = (kb < 500 && n < G4H) ? *(const float4*)(Bw + (size_t)kb * G4H + n) : f40;
        }

        #pragma unroll
        for (int kk = 0; kk < 8; kk++){
            float4 a0 = *(const float4*)(&As[kk][ty*8]);
            float4 a1 = *(const float4*)(&As[kk][ty*8 + 4]);
            const unsigned long long* bp2 = (const unsigned long long*)(&Bs[kk][tx*8]);
            unsigned long long b0 = bp2[0], b1 = bp2[1], b2 = bp2[2], b3 = bp2[3];
            float av[8] = {a0.x,a0.y,a0.z,a0.w,a1.x,a1.y,a1.z,a1.w};
            #pragma unroll
            for (int i = 0; i < 8; i++){
                unsigned long long ad = dup2(av[i]);
                fma2(acc[i][0], ad, b0);
                fma2(acc[i][1], ad, b1);
                fma2(acc[i][2], ad, b2);
                fma2(acc[i][3], ad, b3);
            }
        }
    }

    const int nc = n0 + tx * 8;
    if (nc < G4H){
        float4 bb0 = *(const float4*)(bias + nc);
        float4 bb1 = *(const float4*)(bias + nc + 4);
        #pragma unroll
        for (int i = 0; i < 8; i++){
            int m = m0 + ty*8 + i;
            float o[8];
            unpk2(acc[i][0], o[0], o[1]);
            unpk2(acc[i][1], o[2], o[3]);
            unpk2(acc[i][2], o[4], o[5]);
            unpk2(acc[i][3], o[6], o[7]);
            float4 r0 = make_float4(o[0]+bb0.x, o[1]+bb0.y, o[2]+bb0.z, o[3]+bb0.w);
            float4 r1 = make_float4(o[4]+bb1.x, o[5]+bb1.y, o[6]+bb1.z, o[7]+bb1.w);
            float* cp = Cmat + (size_t)m * G4H + nc;
            *(float4*)(cp)     = r0;
            *(float4*)(cp + 4) = r1;
        }
    }
}

// =====================================================================
// Per-group flat grid barrier (R6, proven).
// =====================================================================
__device__ __forceinline__ void group_barrier(int g, int lt, unsigned &sense)
{
    asm volatile("bar.sync %0, 128;" :: "r"(3 + g) : "memory");
    if (lt == 0){
        unsigned target = sense + 1u;
        unsigned old;
        asm volatile("atom.acq_rel.gpu.global.add.u32 %0, [%1], %2;"
                     : "=r"(old) : "l"(&g_gcnt[g][0]), "r"(1u) : "memory");
        if (old == (unsigned)(NREC_BLOCKS - 1)){
            asm volatile("st.relaxed.gpu.global.u32 [%0], %1;"
                         :: "l"(&g_gcnt[g][0]), "r"(0u) : "memory");
            asm volatile("st.release.gpu.global.u32 [%0], %1;"
                         :: "l"(&g_gsns[g][0]), "r"(target) : "memory");
        } else {
            unsigned v;
            do {
                asm volatile("ld.acquire.gpu.global.u32 %0, [%1];"
                             : "=r"(v) : "l"(&g_gsns[g][0]) : "memory");
            } while ((int)(v - target) < 0);
        }
        sense = target;
    }
    asm volatile("bar.sync %0, 128;" :: "r"(3 + g) : "memory");
}

// =====================================================================
// Persistent LSTM recurrence, two batch-groups per SM, fp16 h exchange.
// h slice (halves): h[g][(k>>2)*128 + (b&31)*4 + (k&3)], 32KB per group.
// Staging primary: one cp.async.bulk (shared::cta dst) of 32KB per group per
// step, gated by an init-time PROBE into scratch (zombie-safe). Fallback:
// per-thread cp.async (16 ops/thread — halved vs fp32 by the fp16 exchange).
// Weights fp32 in SMEM; math fp32 (convert h on load, F2F on alu pipe).
// =====================================================================
__global__ void lstm_rec(const float* __restrict__ xz, const float* __restrict__ Wh,
                         float* __restrict__ hs_out, int store_hs,
                         __half* __restrict__ hb0, __half* __restrict__ hb1)
{
    extern __shared__ char smem[];
    __half* hsm = (__half*)smem;                               // 65536 B (2 x 32KB)
    float*  wsm = (float*)(smem + 65536);                      // 32000 B
    unsigned long long* mbars = (unsigned long long*)(smem + 97536);  // 3 x 8B
    volatile unsigned* s_flag = (volatile unsigned*)(smem + 97560);   // [3]
    const unsigned probe_s = 0;  // set below

    const int tid = threadIdx.x;
    const int g   = tid >> 7;          // batch group 0/1
    const int lt  = tid & 127;         // lane within group
    const int bl  = lt & 31;           // batch within group
    const int u   = (lt >> 5) & 3;     // unit within block slice
    const int u0  = blockIdx.x * 4;
    const int uu  = u0 + u;
    const int b   = g * 32 + bl;       // global batch
    (void)probe_s;

    const unsigned mbar_g  = (unsigned)__cvta_generic_to_shared(&mbars[g]);
    const unsigned mbar_pr = (unsigned)__cvta_generic_to_shared(&mbars[2]);
    const unsigned probe_d = (unsigned)__cvta_generic_to_shared(smem + 97584); // 16B scratch

    unsigned gsense = 0, isense = 0;
    if (lt == 0)
        asm volatile("ld.relaxed.gpu.global.u32 %0, [%1];" : "=r"(gsense) : "l"(&g_gsns[g][0]) : "memory");
    if (tid == 0)
        asm volatile("ld.relaxed.gpu.global.u32 %0, [%1];" : "=r"(isense) : "l"(&g_isns[0]) : "memory");

    // init mbarriers (arrive count 1 = the expect_tx arrival)
    if (tid == 0){
        #pragma unroll
        for (int i = 0; i < 3; i++)
            asm volatile("mbarrier.init.shared.b64 [%0], %1;"
                         :: "r"((unsigned)__cvta_generic_to_shared(&mbars[i])), "r"(1u) : "memory");
    }

    // cache weight slice: wsm[k*16 + uw*4 + gate] = Wh[k*2000 + gate*500 + u0+uw]
    for (int idx = tid; idx < 500 * 16; idx += 256){
        int k = idx >> 4, r = idx & 15;
        int uw = r >> 2, gg = r & 3;
        wsm[idx] = Wh[(size_t)k * G4H + gg * HH + u0 + uw];
    }
    // zero both h buffers (fp16, incl. pad quads)
    {
        int gt = blockIdx.x * 256 + tid;
        uint4 z4 = make_uint4(0, 0, 0, 0);
        for (int i = gt; i < (2 * GSZH) / 8; i += NREC_BLOCKS * 256){
            ((uint4*)hb0)[i] = z4;
            ((uint4*)hb1)[i] = z4;
        }
    }
    __syncthreads();

    // ---- TMA PROBE (once, zombie-safe): 16B bulk copy into scratch ----
    if (tid == 0){
        asm volatile("fence.proxy.async;" ::: "memory");
        asm volatile("mbarrier.arrive.expect_tx.shared.b64 _, [%0], %1;"
                     :: "r"(mbar_pr), "r"(16u) : "memory");
        asm volatile("cp.async.bulk.shared::cta.global.mbarrier::complete_tx::bytes "
                     "[%0], [%1], %2, [%3];"
                     :: "r"(probe_d), "l"((const void*)hb0), "r"(16u), "r"(mbar_pr) : "memory");
        unsigned done = 0;
        int it = 0;
        do {
            asm volatile(
                "{\n\t.reg .pred p;\n\t"
                "mbarrier.try_wait.parity.acquire.cta.shared::cta.b64 p, [%1], %2;\n\t"
                "selp.b32 %0, 1, 0, p;\n\t}"
                : "=r"(done) : "r"(mbar_pr), "r"(0u) : "memory");
        } while (!done && ++it < PROBE_SPIN);
        s_flag[2] = done;
    }
    __syncthreads();
    bool use_tma = (s_flag[2] != 0);

    // init: full-grid barrier so weights/zeros/mbarriers are ready everywhere
    if (tid == 0){
        unsigned target = isense + 1u, old;
        asm volatile("atom.acq_rel.gpu.global.add.u32 %0, [%1], %2;"
                     : "=r"(old) : "l"(&g_icnt[0]), "r"(1u) : "memory");
        if (old == (unsigned)(NREC_BLOCKS - 1)){
            asm volatile("st.relaxed.gpu.global.u32 [%0], %1;" :: "l"(&g_icnt[0]), "r"(0u) : "memory");
            asm volatile("st.release.gpu.global.u32 [%0], %1;" :: "l"(&g_isns[0]), "r"(target) : "memory");
        } else {
            unsigned v;
            do {
                asm volatile("ld.acquire.gpu.global.u32 %0, [%1];" : "=r"(v) : "l"(&g_isns[0]) : "memory");
            } while ((int)(v - target) < 0);
        }
    }
    __syncthreads();

    __half* hsg = hsm + g * GSZH;
    const unsigned hsg_s = (unsigned)__cvta_generic_to_shared(hsg);
    float cst = 0.f;
    const int hoff = g * GSZH + (uu >> 2) * 128 + bl * 4 + (uu & 3);
    const float* xzb = xz + (size_t)b * G4H + uu;
    unsigned ph = 0;                    // mbarrier phase parity

    for (int t = 0; t < TT; t++){
        const __half* hprev = ((t & 1) ? hb1 : hb0) + g * GSZH;
        __half*       hnext = ((t & 1) ? hb0 : hb1);

        // primary: ONE bulk copy (32KB) for this group's slice
        if (use_tma && lt == 0){
            asm volatile("fence.proxy.async;" ::: "memory");
            asm volatile("mbarrier.arrive.expect_tx.shared.b64 _, [%0], %1;"
                         :: "r"(mbar_g), "r"(32768u) : "memory");
            asm volatile("cp.async.bulk.shared::cta.global.mbarrier::complete_tx::bytes "
                         "[%0], [%1], %2, [%3];"
                         :: "r"(hsg_s), "l"((const void*)hprev), "r"(32768u), "r"(mbar_g) : "memory");
        }

        // xz loads (DRAM) fly during the transfer; added at the END (off chain)
        size_t mrow = (size_t)t * BB * G4H;
        float xi = __ldcs(xzb + mrow);
        float xj = __ldcs(xzb + mrow + 500);
        float xf = __ldcs(xzb + mrow + 1000);
        float xo = __ldcs(xzb + mrow + 1500);

        bool staged = false;
        if (use_tma){
            if (lt == 0){
                unsigned done = 0;
                int it = 0;
                do {
                    asm volatile(
                        "{\n\t.reg .pred p;\n\t"
                        "mbarrier.try_wait.parity.acquire.cta.shared::cta.b64 p, [%1], %2;\n\t"
                        "selp.b32 %0, 1, 0, p;\n\t}"
                        : "=r"(done) : "r"(mbar_g), "r"(ph) : "memory");
                } while (!done && ++it < TMA_SPIN_CAP);
                s_flag[g] = done;
            }
            asm volatile("bar.sync %0, 128;" :: "r"(3 + g) : "memory");
            if (s_flag[g]){
                ph ^= 1u;
                staged = true;
            } else {
                use_tma = false;        // permanent fallback (probe made this unlikely)
            }
        }
        if (!staged){
            // fallback: per-thread cp.async staging (32KB = 16 ops/thread)
            #pragma unroll
            for (int i = 0; i < 16; i++){
                int idx = lt + i * 128;
                cp_async16(hsg_s + idx * 16, (const float4*)hprev + idx);
            }
            CP_COMMIT();
            CP_WAIT0();
            asm volatile("bar.sync %0, 128;" :: "r"(3 + g) : "memory");
        }

        unsigned long long aij = 0ULL, afo = 0ULL;
        #pragma unroll 5
        for (int q = 0; q < 125; q++){
            uint2 hraw = *(const uint2*)(hsg + q * 128 + bl * 4);   // 4 halves
            float2 f01 = __half22float2(*(const __half2*)&hraw.x);
            float2 f23 = __half22float2(*(const __half2*)&hraw.y);
            const float* wq = wsm + q * 64 + u * 4;
            ulonglong2 w0 = *(const ulonglong2*)(wq);
            ulonglong2 w1 = *(const ulonglong2*)(wq + 16);
            ulonglong2 w2 = *(const ulonglong2*)(wq + 32);
            ulonglong2 w3 = *(const ulonglong2*)(wq + 48);
            fma2(aij, dup2(f01.x), w0.x); fma2(afo, dup2(f01.x), w0.y);
            fma2(aij, dup2(f01.y), w1.x); fma2(afo, dup2(f01.y), w1.y);
            fma2(aij, dup2(f23.x), w2.x); fma2(afo, dup2(f23.x), w2.y);
            fma2(aij, dup2(f23.y), w3.x); fma2(afo, dup2(f23.y), w3.y);
        }

        float si, sj, sf, so;
        unpk2(aij, si, sj);
        unpk2(afo, sf, so);
        float zi = si + xi, zj = sj + xj, zf = sf + xf, zo = so + xo;

        float ig = 1.f / (1.f + expf(-zi));
        float fg = 1.f / (1.f + expf(-(zf + 1.f)));
        float og = 1.f / (1.f + expf(-zo));
        float jt = tanhf(zj);
        cst = fg * cst + ig * jt;
        float hv = og * tanhf(cst);

        // fp16 store of h (L2-visible, bypass L1)
        unsigned short hv16 = __half_as_ushort(__float2half(hv));
        asm volatile("st.global.cg.u16 [%0], %1;"
                     :: "l"(hnext + hoff), "h"(hv16) : "memory");
        if (store_hs)
            hs_out[(size_t)(t * BB + b) * HH + uu] = hv;   // fp32 for SGEMM2

        group_barrier(g, lt, gsense);
    }
}

// =====================================================================
// Small dense layers. transposed_in: in = fp16 grouped quad-packed h layout.
// =====================================================================
__global__ void dense_kernel(const float* __restrict__ in, const float* __restrict__ W,
                             const float* __restrict__ bias, float* __restrict__ out,
                             int Kdim, int Ndim, int transposed_in, int do_relu)
{
    int gidx = blockIdx.x * blockDim.x + threadIdx.x;
    if (gidx >= BB * Ndim) return;
    int bv = gidx / Ndim;
    int j  = gidx - bv * Ndim;
    float acc = bias[j];
    if (transposed_in){
        const __half* inh = (const __half*)in;
        int base = (bv >> 5) * GSZH + (bv & 31) * 4;
        #pragma unroll 8
        for (int k = 0; k < Kdim; k++)
            acc += __half2float(inh[base + (k >> 2) * 128 + (k & 3)]) * W[k * Ndim + j];
    } else {
        #pragma unroll 8
        for (int k = 0; k < Kdim; k++)
            acc += in[bv * Kdim + k] * W[k * Ndim + j];
    }
    out[gidx] = do_relu ? fmaxf(acc, 0.f) : acc;
}

// =====================================================================
// Launch
// =====================================================================
#define REC_SMEM 97664   // 65536 h-stage + 32000 weights + mbars/flags/probe

extern "C" void kernel_launch(void* const* d_in, const int* in_sizes, int n_in,
                              void* d_out, int out_size)
{
    const int*   X     = (const int*)  d_in[0];
    const float* embed = (const float*)d_in[1];
    const float* k1    = (const float*)d_in[2];
    const float* b1    = (const float*)d_in[3];
    const float* k2    = (const float*)d_in[4];
    const float* b2    = (const float*)d_in[5];
    const float* w1    = (const float*)d_in[6];
    const float* bw1   = (const float*)d_in[7];
    const float* w2    = (const float*)d_in[8];
    const float* bw2   = (const float*)d_in[9];
    const float* wp    = (const float*)d_in[10];
    const float* bp    = (const float*)d_in[11];
    float* out = (float*)d_out;

    float *xz, *hs1, *d1, *d2;
    __half *hb0, *hb1;
    cudaGetSymbolAddress((void**)&xz,  g_xz);
    cudaGetSymbolAddress((void**)&hs1, g_hs1);
    cudaGetSymbolAddress((void**)&hb0, g_hb0);
    cudaGetSymbolAddress((void**)&hb1, g_hb1);
    cudaGetSymbolAddress((void**)&d1,  g_d1);
    cudaGetSymbolAddress((void**)&d2,  g_d2);

    cudaFuncSetAttribute(lstm_rec, cudaFuncAttributeMaxDynamicSharedMemorySize, REC_SMEM);

    dim3 ggrid(16, 200);   // N tiles x M tiles

    // layer 1: xz1 = embed[X] @ k1[:E] + b1 ; then recurrence (stores hs1 fp32)
    sgemm_xz<1><<<ggrid, 256>>>(X, embed, k1, b1, xz);
    lstm_rec<<<NREC_BLOCKS, 256, REC_SMEM>>>(xz, k1 + (size_t)EE * G4H,
                                             hs1, 1, hb0, hb1);

    // layer 2: xz2 = hs1 @ k2[:H] + b2 ; recurrence (final h only)
    sgemm_xz<0><<<ggrid, 256>>>(nullptr, hs1, k2, b2, xz);
    lstm_rec<<<NREC_BLOCKS, 256, REC_SMEM>>>(xz, k2 + (size_t)HH * G4H,
                                             nullptr, 0, hb0, hb1);

    // head: T=400 even -> final h (fp16) in hb0 (written at t=399)
    dense_kernel<<<(BB*DD1 + 255)/256, 256>>>((const float*)hb0, w1, bw1, d1, HH,  DD1, 1, 1);
    dense_kernel<<<(BB*DD2 + 255)/256, 256>>>(d1,  w2, bw2, d2, DD1, DD2, 0, 1);
    dense_kernel<<<1, BB*CC>>>(d2, wp, bp, out, DD2, CC, 0, 0);
}